// round 1
// baseline (speedup 1.0000x reference)
#include <cuda_runtime.h>
#include <math.h>

#define Bdim 128
#define Tdim 256
#define Adim 8
#define Hdim 1024
#define BT (Bdim * Tdim)        // 32768
#define G3H (3 * Hdim)          // 3072

// Scratch (device globals: allocation-free kernel_launch)
__device__ float g_x[(size_t)BT * Hdim];     // [BT, H]   relu(actions@fc_w^T + fc_b)
__device__ float g_xp[(size_t)BT * G3H];     // [BT, 3H]  x@w_ih^T + b_ih

// ---------------------------------------------------------------------------
// Kernel 1: input projection  x[m,h] = relu(fc_b[h] + sum_a act[m,a]*fc_w[h,a])
// ---------------------------------------------------------------------------
__global__ __launch_bounds__(128) void proj_kernel(
    const float* __restrict__ actions,   // [BT, 8]
    const float* __restrict__ fc_w,      // [H, 8]
    const float* __restrict__ fc_b)      // [H]
{
    const int m = blockIdx.x;
    const int t = threadIdx.x;
    __shared__ float act[Adim];
    if (t < Adim) act[t] = actions[m * Adim + t];
    __syncthreads();
    const float a0 = act[0], a1 = act[1], a2 = act[2], a3 = act[3];
    const float a4 = act[4], a5 = act[5], a6 = act[6], a7 = act[7];
#pragma unroll
    for (int j = 0; j < Hdim / 128; j++) {
        const int h = t + j * 128;
        const float4* wp = reinterpret_cast<const float4*>(fc_w + (size_t)h * Adim);
        const float4 w0 = wp[0];
        const float4 w1 = wp[1];
        float v = fc_b[h];
        v += a0 * w0.x + a1 * w0.y + a2 * w0.z + a3 * w0.w;
        v += a4 * w1.x + a5 * w1.y + a6 * w1.z + a7 * w1.w;
        g_x[(size_t)m * Hdim + h] = fmaxf(v, 0.0f);
    }
}

// ---------------------------------------------------------------------------
// Kernel 2: xp GEMM  xp[m,n] = b_ih[n] + sum_k x[m,k] * w_ih[n,k]
// M = 32768, N = 3072, K = 1024.  128x128x8 tiling, 8x8 register tiles.
// ---------------------------------------------------------------------------
#define BM 128
#define BN 128
#define BKx 8

__global__ __launch_bounds__(256) void xp_gemm(
    const float* __restrict__ w_ih,      // [3H, H] (row-major, K contiguous)
    const float* __restrict__ b_ih)      // [3H]
{
    __shared__ float As[BKx][BM];
    __shared__ float Bs[BKx][BN];

    const int n0 = blockIdx.x * BN;      // over 3H (24 blocks)
    const int m0 = blockIdx.y * BM;      // over BT (256 blocks)
    const int tid = threadIdx.x;

    const int tm = (tid >> 4) << 3;      // 0..120 step 8
    const int tn = (tid & 15) << 3;      // 0..120 step 8

    const int lrow = tid >> 1;           // 0..127
    const int lcol = (tid & 1) << 2;     // 0 or 4

    float acc[8][8];
#pragma unroll
    for (int i = 0; i < 8; i++)
#pragma unroll
        for (int j = 0; j < 8; j++) acc[i][j] = 0.0f;

    const float* aptr = &g_x[(size_t)(m0 + lrow) * Hdim + lcol];
    const float* bptr = &w_ih[(size_t)(n0 + lrow) * Hdim + lcol];

    float4 areg = *reinterpret_cast<const float4*>(aptr);
    float4 breg = *reinterpret_cast<const float4*>(bptr);

    for (int k0 = 0; k0 < Hdim; k0 += BKx) {
        As[lcol + 0][lrow] = areg.x;
        As[lcol + 1][lrow] = areg.y;
        As[lcol + 2][lrow] = areg.z;
        As[lcol + 3][lrow] = areg.w;
        Bs[lcol + 0][lrow] = breg.x;
        Bs[lcol + 1][lrow] = breg.y;
        Bs[lcol + 2][lrow] = breg.z;
        Bs[lcol + 3][lrow] = breg.w;
        __syncthreads();

        if (k0 + BKx < Hdim) {
            areg = *reinterpret_cast<const float4*>(aptr + k0 + BKx);
            breg = *reinterpret_cast<const float4*>(bptr + k0 + BKx);
        }

#pragma unroll
        for (int k = 0; k < BKx; k++) {
            float ra[8], rb[8];
#pragma unroll
            for (int i = 0; i < 8; i++) ra[i] = As[k][tm + i];
#pragma unroll
            for (int j = 0; j < 8; j++) rb[j] = Bs[k][tn + j];
#pragma unroll
            for (int i = 0; i < 8; i++)
#pragma unroll
                for (int j = 0; j < 8; j++) acc[i][j] += ra[i] * rb[j];
        }
        __syncthreads();
    }

#pragma unroll
    for (int i = 0; i < 8; i++) {
        const size_t rowoff = (size_t)(m0 + tm + i) * G3H + n0 + tn;
#pragma unroll
        for (int j = 0; j < 8; j++) {
            g_xp[rowoff + j] = acc[i][j] + b_ih[n0 + tn + j];
        }
    }
}

// ---------------------------------------------------------------------------
// Kernel 3: one GRU step.
//   hp[b, g*H+i] = sum_k h[b,k] * w_hh[g*H+i, k] + b_hh[g*H+i]
//   r = sig(xr+hr), z = sig(xz+hz), n = tanh(xn + r*hn)
//   h_new = (1-z)*n + z*h ;  h_t lives at out[:, t, :]
// Tile: 32 b x 32 i, 3 gates, K-chunks of 32. Grid (4, 32) = 128 CTAs.
// ---------------------------------------------------------------------------
__global__ __launch_bounds__(256) void gru_step(
    const float* __restrict__ hprev, int hstride,
    const float* __restrict__ w_hh,       // [3H, H]
    const float* __restrict__ b_hh,       // [3H]
    float* __restrict__ out_t,            // out + t*H ; b-stride = T*H
    int t)
{
    __shared__ float Hs[32][34];
    __shared__ float Ws[3][32][34];

    const int tid = threadIdx.x;
    const int b0 = blockIdx.x * 32;
    const int i0 = blockIdx.y * 32;

    const int row = tid >> 3;            // 0..31
    const int kc  = (tid & 7) << 2;      // 0..28 step 4

    const int b2 = (tid >> 4) << 1;      // 0..30 even
    const int i2 = (tid & 15) << 1;      // 0..30 even

    float accR[4] = {0.f, 0.f, 0.f, 0.f};
    float accZ[4] = {0.f, 0.f, 0.f, 0.f};
    float accN[4] = {0.f, 0.f, 0.f, 0.f};

    const float* hrow = &hprev[(size_t)(b0 + row) * hstride];
    const float* wrow0 = &w_hh[(size_t)(i0 + row) * Hdim];
    const float* wrow1 = &w_hh[(size_t)(Hdim + i0 + row) * Hdim];
    const float* wrow2 = &w_hh[(size_t)(2 * Hdim + i0 + row) * Hdim];

    float4 hreg  = *reinterpret_cast<const float4*>(hrow + kc);
    float4 wreg0 = *reinterpret_cast<const float4*>(wrow0 + kc);
    float4 wreg1 = *reinterpret_cast<const float4*>(wrow1 + kc);
    float4 wreg2 = *reinterpret_cast<const float4*>(wrow2 + kc);

    for (int k0 = 0; k0 < Hdim; k0 += 32) {
        Hs[kc + 0][row] = hreg.x;  Hs[kc + 1][row] = hreg.y;
        Hs[kc + 2][row] = hreg.z;  Hs[kc + 3][row] = hreg.w;
        Ws[0][kc + 0][row] = wreg0.x; Ws[0][kc + 1][row] = wreg0.y;
        Ws[0][kc + 2][row] = wreg0.z; Ws[0][kc + 3][row] = wreg0.w;
        Ws[1][kc + 0][row] = wreg1.x; Ws[1][kc + 1][row] = wreg1.y;
        Ws[1][kc + 2][row] = wreg1.z; Ws[1][kc + 3][row] = wreg1.w;
        Ws[2][kc + 0][row] = wreg2.x; Ws[2][kc + 1][row] = wreg2.y;
        Ws[2][kc + 2][row] = wreg2.z; Ws[2][kc + 3][row] = wreg2.w;
        __syncthreads();

        if (k0 + 32 < Hdim) {
            const int kn = k0 + 32 + kc;
            hreg  = *reinterpret_cast<const float4*>(hrow + kn);
            wreg0 = *reinterpret_cast<const float4*>(wrow0 + kn);
            wreg1 = *reinterpret_cast<const float4*>(wrow1 + kn);
            wreg2 = *reinterpret_cast<const float4*>(wrow2 + kn);
        }

#pragma unroll
        for (int k = 0; k < 32; k++) {
            const float2 hv = *reinterpret_cast<const float2*>(&Hs[k][b2]);
            const float2 w0 = *reinterpret_cast<const float2*>(&Ws[0][k][i2]);
            const float2 w1 = *reinterpret_cast<const float2*>(&Ws[1][k][i2]);
            const float2 w2 = *reinterpret_cast<const float2*>(&Ws[2][k][i2]);
            accR[0] += hv.x * w0.x; accR[1] += hv.x * w0.y;
            accR[2] += hv.y * w0.x; accR[3] += hv.y * w0.y;
            accZ[0] += hv.x * w1.x; accZ[1] += hv.x * w1.y;
            accZ[2] += hv.y * w1.x; accZ[3] += hv.y * w1.y;
            accN[0] += hv.x * w2.x; accN[1] += hv.x * w2.y;
            accN[2] += hv.y * w2.x; accN[3] += hv.y * w2.y;
        }
        __syncthreads();
    }

#pragma unroll
    for (int bb = 0; bb < 2; bb++) {
        const int b = b0 + b2 + bb;
        const float* xprow = &g_xp[((size_t)b * Tdim + t) * G3H];
#pragma unroll
        for (int ii = 0; ii < 2; ii++) {
            const int i = i0 + i2 + ii;
            const int a = bb * 2 + ii;
            const float hr = accR[a] + b_hh[i];
            const float hz = accZ[a] + b_hh[Hdim + i];
            const float hn = accN[a] + b_hh[2 * Hdim + i];
            const float xr = xprow[i];
            const float xz = xprow[Hdim + i];
            const float xn = xprow[2 * Hdim + i];
            const float r = 1.0f / (1.0f + expf(-(xr + hr)));
            const float z = 1.0f / (1.0f + expf(-(xz + hz)));
            const float n = tanhf(xn + r * hn);
            const float hv = hprev[(size_t)b * hstride + i];
            out_t[(size_t)b * (Tdim * Hdim) + i] = (1.0f - z) * n + z * hv;
        }
    }
}

// ---------------------------------------------------------------------------
extern "C" void kernel_launch(void* const* d_in, const int* in_sizes, int n_in,
                              void* d_out, int out_size)
{
    const float* actions = (const float*)d_in[0];   // [B,T,A]
    const float* hidden  = (const float*)d_in[1];   // [B,H]
    const float* fc_w    = (const float*)d_in[2];   // [H,A]
    const float* fc_b    = (const float*)d_in[3];   // [H]
    const float* w_ih    = (const float*)d_in[4];   // [3H,H]
    const float* w_hh    = (const float*)d_in[5];   // [3H,H]
    const float* b_ih    = (const float*)d_in[6];   // [3H]
    const float* b_hh    = (const float*)d_in[7];   // [3H]
    float* out = (float*)d_out;                     // [B,T,H]

    proj_kernel<<<BT, 128>>>(actions, fc_w, fc_b);
    xp_gemm<<<dim3(G3H / BN, BT / BM), 256>>>(w_ih, b_ih);

    for (int t = 0; t < Tdim; t++) {
        const float* hprev = (t == 0) ? hidden : (out + (size_t)(t - 1) * Hdim);
        const int hstride  = (t == 0) ? Hdim : (Tdim * Hdim);
        gru_step<<<dim3(Bdim / 32, Hdim / 32), 256>>>(
            hprev, hstride, w_hh, b_hh, out + (size_t)t * Hdim, t);
    }
}

// round 2
// speedup vs baseline: 1.0531x; 1.0531x over previous
#include <cuda_runtime.h>
#include <math.h>

#define Bdim 128
#define Tdim 256
#define Adim 8
#define Hdim 1024
#define BT (Bdim * Tdim)        // 32768
#define G3H (3 * Hdim)          // 3072

// Scratch (device globals: allocation-free kernel_launch)
__device__ float g_x[(size_t)BT * Hdim];     // [BT, H]   relu(actions@fc_w^T + fc_b)
__device__ float g_xp[(size_t)BT * G3H];     // [BT, 3H]  x@w_ih^T + b_ih

// ---------------------------------------------------------------------------
// Kernel 1: input projection  x[m,h] = relu(fc_b[h] + sum_a act[m,a]*fc_w[h,a])
// ---------------------------------------------------------------------------
__global__ __launch_bounds__(128) void proj_kernel(
    const float* __restrict__ actions,   // [BT, 8]
    const float* __restrict__ fc_w,      // [H, 8]
    const float* __restrict__ fc_b)      // [H]
{
    const int m = blockIdx.x;
    const int t = threadIdx.x;
    __shared__ float act[Adim];
    if (t < Adim) act[t] = actions[m * Adim + t];
    __syncthreads();
    const float a0 = act[0], a1 = act[1], a2 = act[2], a3 = act[3];
    const float a4 = act[4], a5 = act[5], a6 = act[6], a7 = act[7];
#pragma unroll
    for (int j = 0; j < Hdim / 128; j++) {
        const int h = t + j * 128;
        const float4* wp = reinterpret_cast<const float4*>(fc_w + (size_t)h * Adim);
        const float4 w0 = wp[0];
        const float4 w1 = wp[1];
        float v = fc_b[h];
        v += a0 * w0.x + a1 * w0.y + a2 * w0.z + a3 * w0.w;
        v += a4 * w1.x + a5 * w1.y + a6 * w1.z + a7 * w1.w;
        g_x[(size_t)m * Hdim + h] = fmaxf(v, 0.0f);
    }
}

// ---------------------------------------------------------------------------
// Kernel 2: xp GEMM  xp[m,n] = b_ih[n] + sum_k x[m,k] * w_ih[n,k]
// M = 32768, N = 3072, K = 1024.  128x128x8 tiling, 8x8 register tiles.
// ---------------------------------------------------------------------------
#define BM 128
#define BN 128
#define BKx 8

__global__ __launch_bounds__(256) void xp_gemm(
    const float* __restrict__ w_ih,      // [3H, H] (row-major, K contiguous)
    const float* __restrict__ b_ih)      // [3H]
{
    __shared__ float As[BKx][BM];
    __shared__ float Bs[BKx][BN];

    const int n0 = blockIdx.x * BN;      // over 3H (24 blocks)
    const int m0 = blockIdx.y * BM;      // over BT (256 blocks)
    const int tid = threadIdx.x;

    const int tm = (tid >> 4) << 3;      // 0..120 step 8
    const int tn = (tid & 15) << 3;      // 0..120 step 8

    const int lrow = tid >> 1;           // 0..127
    const int lcol = (tid & 1) << 2;     // 0 or 4

    float acc[8][8];
#pragma unroll
    for (int i = 0; i < 8; i++)
#pragma unroll
        for (int j = 0; j < 8; j++) acc[i][j] = 0.0f;

    const float* aptr = &g_x[(size_t)(m0 + lrow) * Hdim + lcol];
    const float* bptr = &w_ih[(size_t)(n0 + lrow) * Hdim + lcol];

    float4 areg = *reinterpret_cast<const float4*>(aptr);
    float4 breg = *reinterpret_cast<const float4*>(bptr);

    for (int k0 = 0; k0 < Hdim; k0 += BKx) {
        As[lcol + 0][lrow] = areg.x;
        As[lcol + 1][lrow] = areg.y;
        As[lcol + 2][lrow] = areg.z;
        As[lcol + 3][lrow] = areg.w;
        Bs[lcol + 0][lrow] = breg.x;
        Bs[lcol + 1][lrow] = breg.y;
        Bs[lcol + 2][lrow] = breg.z;
        Bs[lcol + 3][lrow] = breg.w;
        __syncthreads();

        if (k0 + BKx < Hdim) {
            areg = *reinterpret_cast<const float4*>(aptr + k0 + BKx);
            breg = *reinterpret_cast<const float4*>(bptr + k0 + BKx);
        }

#pragma unroll
        for (int k = 0; k < BKx; k++) {
            float ra[8], rb[8];
#pragma unroll
            for (int i = 0; i < 8; i++) ra[i] = As[k][tm + i];
#pragma unroll
            for (int j = 0; j < 8; j++) rb[j] = Bs[k][tn + j];
#pragma unroll
            for (int i = 0; i < 8; i++)
#pragma unroll
                for (int j = 0; j < 8; j++) acc[i][j] += ra[i] * rb[j];
        }
        __syncthreads();
    }

#pragma unroll
    for (int i = 0; i < 8; i++) {
        const size_t rowoff = (size_t)(m0 + tm + i) * G3H + n0 + tn;
#pragma unroll
        for (int j = 0; j < 8; j++) {
            g_xp[rowoff + j] = acc[i][j] + b_ih[n0 + tn + j];
        }
    }
}

// ---------------------------------------------------------------------------
// Kernel 3: one GRU step.
//   hp[b, g*H+i] = sum_k h[b,k] * w_hh[g*H+i, k] + b_hh[g*H+i]
//   r = sig(xr+hr), z = sig(xz+hz), n = tanh(xn + r*hn)
//   h_new = (1-z)*n + z*h ;  h_t lives at out[:, t, :]
// Tile: 32 b x 32 i, 3 gates, K-chunks of 32. Grid (4, 32) = 128 CTAs.
// ---------------------------------------------------------------------------
__global__ __launch_bounds__(256) void gru_step(
    const float* __restrict__ hprev, int hstride,
    const float* __restrict__ w_hh,       // [3H, H]
    const float* __restrict__ b_hh,       // [3H]
    float* __restrict__ out_t,            // out + t*H ; b-stride = T*H
    int t)
{
    __shared__ float Hs[32][34];
    __shared__ float Ws[3][32][34];

    const int tid = threadIdx.x;
    const int b0 = blockIdx.x * 32;
    const int i0 = blockIdx.y * 32;

    const int row = tid >> 3;            // 0..31
    const int kc  = (tid & 7) << 2;      // 0..28 step 4

    const int b2 = (tid >> 4) << 1;      // 0..30 even
    const int i2 = (tid & 15) << 1;      // 0..30 even

    float accR[4] = {0.f, 0.f, 0.f, 0.f};
    float accZ[4] = {0.f, 0.f, 0.f, 0.f};
    float accN[4] = {0.f, 0.f, 0.f, 0.f};

    const float* hrow = &hprev[(size_t)(b0 + row) * hstride];
    const float* wrow0 = &w_hh[(size_t)(i0 + row) * Hdim];
    const float* wrow1 = &w_hh[(size_t)(Hdim + i0 + row) * Hdim];
    const float* wrow2 = &w_hh[(size_t)(2 * Hdim + i0 + row) * Hdim];

    float4 hreg  = *reinterpret_cast<const float4*>(hrow + kc);
    float4 wreg0 = *reinterpret_cast<const float4*>(wrow0 + kc);
    float4 wreg1 = *reinterpret_cast<const float4*>(wrow1 + kc);
    float4 wreg2 = *reinterpret_cast<const float4*>(wrow2 + kc);

    for (int k0 = 0; k0 < Hdim; k0 += 32) {
        Hs[kc + 0][row] = hreg.x;  Hs[kc + 1][row] = hreg.y;
        Hs[kc + 2][row] = hreg.z;  Hs[kc + 3][row] = hreg.w;
        Ws[0][kc + 0][row] = wreg0.x; Ws[0][kc + 1][row] = wreg0.y;
        Ws[0][kc + 2][row] = wreg0.z; Ws[0][kc + 3][row] = wreg0.w;
        Ws[1][kc + 0][row] = wreg1.x; Ws[1][kc + 1][row] = wreg1.y;
        Ws[1][kc + 2][row] = wreg1.z; Ws[1][kc + 3][row] = wreg1.w;
        Ws[2][kc + 0][row] = wreg2.x; Ws[2][kc + 1][row] = wreg2.y;
        Ws[2][kc + 2][row] = wreg2.z; Ws[2][kc + 3][row] = wreg2.w;
        __syncthreads();

        if (k0 + 32 < Hdim) {
            const int kn = k0 + 32 + kc;
            hreg  = *reinterpret_cast<const float4*>(hrow + kn);
            wreg0 = *reinterpret_cast<const float4*>(wrow0 + kn);
            wreg1 = *reinterpret_cast<const float4*>(wrow1 + kn);
            wreg2 = *reinterpret_cast<const float4*>(wrow2 + kn);
        }

#pragma unroll
        for (int k = 0; k < 32; k++) {
            const float2 hv = *reinterpret_cast<const float2*>(&Hs[k][b2]);
            const float2 w0 = *reinterpret_cast<const float2*>(&Ws[0][k][i2]);
            const float2 w1 = *reinterpret_cast<const float2*>(&Ws[1][k][i2]);
            const float2 w2 = *reinterpret_cast<const float2*>(&Ws[2][k][i2]);
            accR[0] += hv.x * w0.x; accR[1] += hv.x * w0.y;
            accR[2] += hv.y * w0.x; accR[3] += hv.y * w0.y;
            accZ[0] += hv.x * w1.x; accZ[1] += hv.x * w1.y;
            accZ[2] += hv.y * w1.x; accZ[3] += hv.y * w1.y;
            accN[0] += hv.x * w2.x; accN[1] += hv.x * w2.y;
            accN[2] += hv.y * w2.x; accN[3] += hv.y * w2.y;
        }
        __syncthreads();
    }

#pragma unroll
    for (int bb = 0; bb < 2; bb++) {
        const int b = b0 + b2 + bb;
        const float* xprow = &g_xp[((size_t)b * Tdim + t) * G3H];
#pragma unroll
        for (int ii = 0; ii < 2; ii++) {
            const int i = i0 + i2 + ii;
            const int a = bb * 2 + ii;
            const float hr = accR[a] + b_hh[i];
            const float hz = accZ[a] + b_hh[Hdim + i];
            const float hn = accN[a] + b_hh[2 * Hdim + i];
            const float xr = xprow[i];
            const float xz = xprow[Hdim + i];
            const float xn = xprow[2 * Hdim + i];
            const float r = 1.0f / (1.0f + expf(-(xr + hr)));
            const float z = 1.0f / (1.0f + expf(-(xz + hz)));
            const float n = tanhf(xn + r * hn);
            const float hv = hprev[(size_t)b * hstride + i];
            out_t[(size_t)b * (Tdim * Hdim) + i] = (1.0f - z) * n + z * hv;
        }
    }
}

// ---------------------------------------------------------------------------
extern "C" void kernel_launch(void* const* d_in, const int* in_sizes, int n_in,
                              void* d_out, int out_size)
{
    const float* actions = (const float*)d_in[0];   // [B,T,A]
    const float* hidden  = (const float*)d_in[1];   // [B,H]
    const float* fc_w    = (const float*)d_in[2];   // [H,A]
    const float* fc_b    = (const float*)d_in[3];   // [H]
    const float* w_ih    = (const float*)d_in[4];   // [3H,H]
    const float* w_hh    = (const float*)d_in[5];   // [3H,H]
    const float* b_ih    = (const float*)d_in[6];   // [3H]
    const float* b_hh    = (const float*)d_in[7];   // [3H]
    float* out = (float*)d_out;                     // [B,T,H]

    proj_kernel<<<BT, 128>>>(actions, fc_w, fc_b);
    xp_gemm<<<dim3(G3H / BN, BT / BM), 256>>>(w_ih, b_ih);

    for (int t = 0; t < Tdim; t++) {
        const float* hprev = (t == 0) ? hidden : (out + (size_t)(t - 1) * Hdim);
        const int hstride  = (t == 0) ? Hdim : (Tdim * Hdim);
        gru_step<<<dim3(Bdim / 32, Hdim / 32), 256>>>(
            hprev, hstride, w_hh, b_hh, out + (size_t)t * Hdim, t);
    }
}

// round 4
// speedup vs baseline: 2.1898x; 2.0793x over previous
#include <cuda_runtime.h>
#include <cuda_bf16.h>
#include <math.h>
#include <stdint.h>

#define Bdim 128
#define Tdim 256
#define Adim 8
#define Hdim 1024
#define BT   (Bdim * Tdim)        // 32768
#define G3H  (3 * Hdim)           // 3072
#define KC   3072                 // concat K for split-bf16 GEMM
#define NCH  48                   // K chunks of 64

// ---------------- device scratch ----------------
__device__ float g_xp[(size_t)BT * G3H];                 // [BT,3H] fp32
__device__ __nv_bfloat16 g_Axp[(size_t)BT * KC];         // [x1|x1|x2]
__device__ __nv_bfloat16 g_Bih[(size_t)G3H * KC];        // row n: [w1|w2|w1]
__device__ __nv_bfloat16 g_Bhh[(size_t)G3H * KC];        // row j=3i+g: [w1|w2|w1]
__device__ __nv_bfloat16 g_Ah[2][(size_t)Bdim * KC];     // [h1|h1|h2] ping-pong

// ---------------- helpers ----------------
__device__ __forceinline__ uint32_t smem_to_u32(const void* p) {
    uint32_t a;
    asm("{ .reg .u64 t; cvta.to.shared.u64 t, %1; cvt.u32.u64 %0, t; }" : "=r"(a) : "l"(p));
    return a;
}
__device__ __forceinline__ void ldsm4(uint32_t* r, uint32_t a) {
    asm volatile("ldmatrix.sync.aligned.m8n8.x4.shared.b16 {%0,%1,%2,%3}, [%4];"
        : "=r"(r[0]), "=r"(r[1]), "=r"(r[2]), "=r"(r[3]) : "r"(a));
}
__device__ __forceinline__ void mma16816(float* d, const uint32_t* a, const uint32_t* b) {
    asm volatile("mma.sync.aligned.m16n8k16.row.col.f32.bf16.bf16.f32 "
        "{%0,%1,%2,%3}, {%4,%5,%6,%7}, {%8,%9}, {%0,%1,%2,%3};"
        : "+f"(d[0]), "+f"(d[1]), "+f"(d[2]), "+f"(d[3])
        : "r"(a[0]), "r"(a[1]), "r"(a[2]), "r"(a[3]), "r"(b[0]), "r"(b[1]));
}
#define CP_ASYNC16(d, s) asm volatile("cp.async.cg.shared.global [%0], [%1], 16;" :: "r"(d), "l"(s))
#define CP_COMMIT()      asm volatile("cp.async.commit_group;" ::: "memory")
#define CP_WAIT2()       asm volatile("cp.async.wait_group 2;" ::: "memory")
#define SWZ(o) ((o) ^ (((o) >> 3) & 0x70))

// ---------------- kernel 1: proj + split  ([x1|x1|x2]) ------------------
__global__ __launch_bounds__(128) void proj_split(
    const float* __restrict__ actions, const float* __restrict__ fc_w,
    const float* __restrict__ fc_b)
{
    const int m = blockIdx.x, t = threadIdx.x;
    __shared__ float act[Adim];
    if (t < Adim) act[t] = actions[m * Adim + t];
    __syncthreads();
    const float a0 = act[0], a1 = act[1], a2 = act[2], a3 = act[3];
    const float a4 = act[4], a5 = act[5], a6 = act[6], a7 = act[7];
    __nv_bfloat16* dst = g_Axp + (size_t)m * KC;
#pragma unroll
    for (int j = 0; j < Hdim / 128; j++) {
        const int h = t + j * 128;
        const float4* wp = reinterpret_cast<const float4*>(fc_w + (size_t)h * Adim);
        const float4 w0 = wp[0], w1 = wp[1];
        float v = fc_b[h];
        v += a0 * w0.x + a1 * w0.y + a2 * w0.z + a3 * w0.w;
        v += a4 * w1.x + a5 * w1.y + a6 * w1.z + a7 * w1.w;
        v = fmaxf(v, 0.0f);
        const __nv_bfloat16 x1 = __float2bfloat16(v);
        const __nv_bfloat16 x2 = __float2bfloat16(v - __bfloat162float(x1));
        dst[h] = x1; dst[Hdim + h] = x1; dst[2 * Hdim + h] = x2;
    }
}

// ---------------- kernel 2: weight splits -------------------------------
// bid < 3072: g_Bih row n = bid          (w_ih row n)       cols [w1|w2|w1]
// bid >= 3072: g_Bhh row j = bid-3072    (w_hh row g*H+i, j=3i+g)
__global__ __launch_bounds__(256) void split_w(
    const float* __restrict__ w_ih, const float* __restrict__ w_hh)
{
    const int bid = blockIdx.x;
    const float* src;
    __nv_bfloat16* dst;
    if (bid < G3H) {
        src = w_ih + (size_t)bid * Hdim;
        dst = g_Bih + (size_t)bid * KC;
    } else {
        const int j = bid - G3H, g = j % 3, i = j / 3;
        src = w_hh + (size_t)(g * Hdim + i) * Hdim;
        dst = g_Bhh + (size_t)j * KC;
    }
#pragma unroll
    for (int u = 0; u < Hdim / 256; u++) {
        const int k = threadIdx.x + u * 256;
        const float w = src[k];
        const __nv_bfloat16 w1 = __float2bfloat16(w);
        const __nv_bfloat16 w2 = __float2bfloat16(w - __bfloat162float(w1));
        dst[k] = w1; dst[Hdim + k] = w2; dst[2 * Hdim + k] = w1;
    }
}

// ---------------- kernel 3: split hidden -> g_Ah[0] ---------------------
__global__ __launch_bounds__(256) void split_h0(const float* __restrict__ hidden)
{
    const int b = blockIdx.x;
    __nv_bfloat16* dst = g_Ah[0] + (size_t)b * KC;
    const float* src = hidden + (size_t)b * Hdim;
#pragma unroll
    for (int u = 0; u < Hdim / 256; u++) {
        const int k = threadIdx.x + u * 256;
        const float h = src[k];
        const __nv_bfloat16 h1 = __float2bfloat16(h);
        const __nv_bfloat16 h2 = __float2bfloat16(h - __bfloat162float(h1));
        dst[k] = h1; dst[Hdim + k] = h1; dst[2 * Hdim + k] = h2;
    }
}

// ---------------- kernel 4: xp GEMM via mma.sync ------------------------
// Tile 128x96, K=3072. grid(32, 256). 256 thr, 8 warps (warp: 32x48).
// Stage: A 128x128B @0 (16KB), B 96x128B @16384 (12KB) -> 28672 B, 4 stages.
#define XP_STAGE 28672
#define XP_SMEM  (4 * XP_STAGE)

__global__ __launch_bounds__(256) void xp_mma(const float* __restrict__ b_ih)
{
    extern __shared__ char sm[];
    const uint32_t smb = smem_to_u32(sm);
    const int tid = threadIdx.x, lane = tid & 31, wid = tid >> 5;
    const int nb = blockIdx.x, mb = blockIdx.y;

    uint32_t sdst[7]; const char* gsrc[7];
#pragma unroll
    for (int u = 0; u < 7; u++) {
        const int sidx = tid + u * 256;
        if (sidx < 1024) {
            const int row = sidx >> 3, s8 = sidx & 7;
            sdst[u] = SWZ((uint32_t)(row * 128 + s8 * 16));
            gsrc[u] = (const char*)g_Axp + (size_t)(mb * 128 + row) * (KC * 2) + s8 * 16;
        } else {
            const int bx = sidx - 1024, row = bx >> 3, s8 = bx & 7;
            sdst[u] = 16384u + SWZ((uint32_t)(row * 128 + s8 * 16));
            gsrc[u] = (const char*)g_Bih + (size_t)(nb * 96 + row) * (KC * 2) + s8 * 16;
        }
    }
    auto prefetch = [&](int c) {
        if (c < NCH) {
            const uint32_t sb = smb + (uint32_t)(c & 3) * XP_STAGE;
            const size_t off = (size_t)c * 128;
#pragma unroll
            for (int u = 0; u < 7; u++) CP_ASYNC16(sb + sdst[u], gsrc[u] + off);
        }
        CP_COMMIT();
    };

    const int mrow0 = (wid & 3) * 32, nc0 = (wid >> 2) * 48;
    const uint32_t ar0 = mrow0 + (lane & 15), ar1 = ar0 + 16;
    const uint32_t aoff0 = ar0 * 128, amk0 = (ar0 & 7) << 4;
    const uint32_t aoff1 = ar1 * 128, amk1 = (ar1 & 7) << 4;
    const uint32_t akh = (uint32_t)(lane >> 4) * 16;
    uint32_t boff[3], bmk[3];
#pragma unroll
    for (int p = 0; p < 3; p++) {
        const uint32_t nr = nc0 + p * 16 + (lane >> 4) * 8 + (lane & 7);
        boff[p] = 16384u + nr * 128; bmk[p] = (nr & 7) << 4;
    }
    const uint32_t bkh = (uint32_t)((lane >> 3) & 1) * 16;

    float acc[2][6][4] = {};
    prefetch(0); prefetch(1); prefetch(2);
    for (int c = 0; c < NCH; c++) {
        CP_WAIT2();
        __syncthreads();
        prefetch(c + 3);
        const uint32_t sb = smb + (uint32_t)(c & 3) * XP_STAGE;
#pragma unroll
        for (int s = 0; s < 4; s++) {
            uint32_t a0[4], a1[4], b[12];
            const uint32_t cA = akh + s * 32, cB = bkh + s * 32;
            ldsm4(a0, sb + aoff0 + (cA ^ amk0));
            ldsm4(a1, sb + aoff1 + (cA ^ amk1));
#pragma unroll
            for (int p = 0; p < 3; p++) ldsm4(b + 4 * p, sb + boff[p] + (cB ^ bmk[p]));
#pragma unroll
            for (int nt = 0; nt < 6; nt++) {
                mma16816(acc[0][nt], a0, b + 2 * nt);
                mma16816(acc[1][nt], a1, b + 2 * nt);
            }
        }
    }

    const int q = lane & 3, r4 = lane >> 2;
#pragma unroll
    for (int mg = 0; mg < 2; mg++) {
        const int row = mb * 128 + mrow0 + mg * 16 + r4;
#pragma unroll
        for (int nt = 0; nt < 6; nt++) {
            const int col = nb * 96 + nc0 + nt * 8 + 2 * q;
            const float2 bias = *reinterpret_cast<const float2*>(b_ih + col);
            float2 v0, v1;
            v0.x = acc[mg][nt][0] + bias.x; v0.y = acc[mg][nt][1] + bias.y;
            v1.x = acc[mg][nt][2] + bias.x; v1.y = acc[mg][nt][3] + bias.y;
            *reinterpret_cast<float2*>(g_xp + (size_t)row * G3H + col) = v0;
            *reinterpret_cast<float2*>(g_xp + (size_t)(row + 8) * G3H + col) = v1;
        }
    }
}

// ---------------- kernel 5: GRU step via mma.sync -----------------------
// Tile 32x96, K=3072. grid(32, 4). 128 thr, 4 warps (warp: 16x48).
// Stage: A 32x128B @0 (4KB), B 96x128B @4096 (12KB) -> 16384 B, 4 stages.
#define GR_STAGE 16384
#define GR_SMEM  (4 * GR_STAGE)

__global__ __launch_bounds__(128) void gru_mma(
    int t, const float* __restrict__ hidden,
    const float* __restrict__ b_hh, float* __restrict__ out)
{
    extern __shared__ char sm[];
    const uint32_t smb = smem_to_u32(sm);
    const int tid = threadIdx.x, lane = tid & 31, wid = tid >> 5;
    const int nb = blockIdx.x, mb = blockIdx.y;
    const int par = t & 1;

    uint32_t sdst[8]; const char* gsrc[8];
#pragma unroll
    for (int u = 0; u < 8; u++) {
        const int sidx = tid + u * 128;
        if (sidx < 256) {
            const int row = sidx >> 3, s8 = sidx & 7;
            sdst[u] = SWZ((uint32_t)(row * 128 + s8 * 16));
            gsrc[u] = (const char*)g_Ah[par] + (size_t)(mb * 32 + row) * (KC * 2) + s8 * 16;
        } else {
            const int bx = sidx - 256, row = bx >> 3, s8 = bx & 7;
            sdst[u] = 4096u + SWZ((uint32_t)(row * 128 + s8 * 16));
            gsrc[u] = (const char*)g_Bhh + (size_t)(nb * 96 + row) * (KC * 2) + s8 * 16;
        }
    }
    auto prefetch = [&](int c) {
        if (c < NCH) {
            const uint32_t sb = smb + (uint32_t)(c & 3) * GR_STAGE;
            const size_t off = (size_t)c * 128;
#pragma unroll
            for (int u = 0; u < 8; u++) CP_ASYNC16(sb + sdst[u], gsrc[u] + off);
        }
        CP_COMMIT();
    };

    const int mrow0 = (wid & 1) * 16, nc0 = (wid >> 1) * 48;
    const uint32_t ar = mrow0 + (lane & 15);
    const uint32_t aoff = ar * 128, amk = (ar & 7) << 4;
    const uint32_t akh = (uint32_t)(lane >> 4) * 16;
    uint32_t boff[3], bmk[3];
#pragma unroll
    for (int p = 0; p < 3; p++) {
        const uint32_t nr = nc0 + p * 16 + (lane >> 4) * 8 + (lane & 7);
        boff[p] = 4096u + nr * 128; bmk[p] = (nr & 7) << 4;
    }
    const uint32_t bkh = (uint32_t)((lane >> 3) & 1) * 16;

    float acc[6][4] = {};
    prefetch(0); prefetch(1); prefetch(2);
    for (int c = 0; c < NCH; c++) {
        CP_WAIT2();
        __syncthreads();
        prefetch(c + 3);
        const uint32_t sb = smb + (uint32_t)(c & 3) * GR_STAGE;
#pragma unroll
        for (int s = 0; s < 4; s++) {
            uint32_t a[4], b[12];
            const uint32_t cA = akh + s * 32, cB = bkh + s * 32;
            ldsm4(a, sb + aoff + (cA ^ amk));
#pragma unroll
            for (int p = 0; p < 3; p++) ldsm4(b + 4 * p, sb + boff[p] + (cB ^ bmk[p]));
#pragma unroll
            for (int nt = 0; nt < 6; nt++) mma16816(acc[nt], a, b + 2 * nt);
        }
    }

    // stage hp tile [32][100] fp32 in smem (overlays stages; all reads done)
    float* hp = reinterpret_cast<float*>(sm);
    __syncthreads();
    {
        const int q = lane & 3, r4 = lane >> 2;
        const int r0 = mrow0 + r4;
#pragma unroll
        for (int nt = 0; nt < 6; nt++) {
            const int cc = nc0 + nt * 8 + 2 * q;
            hp[r0 * 100 + cc]           = acc[nt][0];
            hp[r0 * 100 + cc + 1]       = acc[nt][1];
            hp[(r0 + 8) * 100 + cc]     = acc[nt][2];
            hp[(r0 + 8) * 100 + cc + 1] = acc[nt][3];
        }
    }
    __syncthreads();

    // gate epilogue: 32 b x 32 triples, 8 per thread
    const int b0 = mb * 32, i0 = nb * 32;
    __nv_bfloat16* Abase = g_Ah[par ^ 1];
#pragma unroll
    for (int u = 0; u < 8; u++) {
        const int idx = tid + u * 128;
        const int bl = idx >> 5, il = idx & 31;
        const int b = b0 + bl, i = i0 + il;
        const float hr = hp[bl * 100 + 3 * il + 0] + b_hh[i];
        const float hz = hp[bl * 100 + 3 * il + 1] + b_hh[Hdim + i];
        const float hn = hp[bl * 100 + 3 * il + 2] + b_hh[2 * Hdim + i];
        const float* xpr = g_xp + ((size_t)b * Tdim + t) * G3H;
        const float xr = xpr[i], xz = xpr[Hdim + i], xn = xpr[2 * Hdim + i];
        const float rg = 1.0f / (1.0f + expf(-(xr + hr)));
        const float zg = 1.0f / (1.0f + expf(-(xz + hz)));
        const float ng = tanhf(xn + rg * hn);
        const float hv = (t == 0) ? hidden[(size_t)b * Hdim + i]
                                  : out[((size_t)b * Tdim + (t - 1)) * Hdim + i];
        const float hnew = (1.0f - zg) * ng + zg * hv;
        out[((size_t)b * Tdim + t) * Hdim + i] = hnew;
        const __nv_bfloat16 h1 = __float2bfloat16(hnew);
        const __nv_bfloat16 h2 = __float2bfloat16(hnew - __bfloat162float(h1));
        __nv_bfloat16* An = Abase + (size_t)b * KC;
        An[i] = h1; An[Hdim + i] = h1; An[2 * Hdim + i] = h2;
    }
}

// ---------------------------------------------------------------------------
extern "C" void kernel_launch(void* const* d_in, const int* in_sizes, int n_in,
                              void* d_out, int out_size)
{
    const float* actions = (const float*)d_in[0];
    const float* hidden  = (const float*)d_in[1];
    const float* fc_w    = (const float*)d_in[2];
    const float* fc_b    = (const float*)d_in[3];
    const float* w_ih    = (const float*)d_in[4];
    const float* w_hh    = (const float*)d_in[5];
    const float* b_ih    = (const float*)d_in[6];
    const float* b_hh    = (const float*)d_in[7];
    float* out = (float*)d_out;

    static bool attr_set = false;
    if (!attr_set) {
        cudaFuncSetAttribute(xp_mma, cudaFuncAttributeMaxDynamicSharedMemorySize, XP_SMEM);
        cudaFuncSetAttribute(gru_mma, cudaFuncAttributeMaxDynamicSharedMemorySize, GR_SMEM);
        attr_set = true;
    }

    proj_split<<<BT, 128>>>(actions, fc_w, fc_b);
    split_w<<<2 * G3H, 256>>>(w_ih, w_hh);
    split_h0<<<Bdim, 256>>>(hidden);
    xp_mma<<<dim3(32, 256), 256, XP_SMEM>>>(b_ih);

    for (int t = 0; t < Tdim; t++)
        gru_mma<<<dim3(32, 4), 128, GR_SMEM>>>(t, hidden, b_hh, out);
}

// round 5
// speedup vs baseline: 2.3486x; 1.0725x over previous
#include <cuda_runtime.h>
#include <cuda_bf16.h>
#include <math.h>
#include <stdint.h>

#define Bdim 128
#define Tdim 256
#define Adim 8
#define Hdim 1024
#define BT   (Bdim * Tdim)        // 32768
#define G3H  (3 * Hdim)           // 3072
#define KC   3072                 // concat K for split-bf16 GEMM
#define NCH  48                   // K chunks of 64

// ---------------- device scratch ----------------
__device__ float g_xp[(size_t)BT * G3H];                 // [BT,3H] fp32
__device__ __nv_bfloat16 g_Axp[(size_t)BT * KC];         // [x1|x1|x2]
__device__ __nv_bfloat16 g_Bih[(size_t)G3H * KC];        // row n: [w1|w2|w1]
__device__ __nv_bfloat16 g_Bhh[(size_t)G3H * KC];        // row j=3i+g: [w1|w2|w1]
__device__ __nv_bfloat16 g_Ah[2][(size_t)Bdim * KC];     // [h1|h1|h2] ping-pong
__device__ unsigned g_bar_count;
__device__ unsigned g_bar_flag;

// ---------------- helpers ----------------
__device__ __forceinline__ uint32_t smem_to_u32(const void* p) {
    uint32_t a;
    asm("{ .reg .u64 t; cvta.to.shared.u64 t, %1; cvt.u32.u64 %0, t; }" : "=r"(a) : "l"(p));
    return a;
}
__device__ __forceinline__ void ldsm4(uint32_t* r, uint32_t a) {
    asm volatile("ldmatrix.sync.aligned.m8n8.x4.shared.b16 {%0,%1,%2,%3}, [%4];"
        : "=r"(r[0]), "=r"(r[1]), "=r"(r[2]), "=r"(r[3]) : "r"(a));
}
__device__ __forceinline__ void mma16816(float* d, const uint32_t* a, const uint32_t* b) {
    asm volatile("mma.sync.aligned.m16n8k16.row.col.f32.bf16.bf16.f32 "
        "{%0,%1,%2,%3}, {%4,%5,%6,%7}, {%8,%9}, {%0,%1,%2,%3};"
        : "+f"(d[0]), "+f"(d[1]), "+f"(d[2]), "+f"(d[3])
        : "r"(a[0]), "r"(a[1]), "r"(a[2]), "r"(a[3]), "r"(b[0]), "r"(b[1]));
}
#define CP_ASYNC16(d, s) asm volatile("cp.async.cg.shared.global [%0], [%1], 16;" :: "r"(d), "l"(s))
#define CP_COMMIT()      asm volatile("cp.async.commit_group;" ::: "memory")
#define CP_WAIT2()       asm volatile("cp.async.wait_group 2;" ::: "memory")
#define SWZ(o) ((o) ^ (((o) >> 3) & 0x70))

// ---------------- kernel 1: proj + split  ([x1|x1|x2]) ------------------
__global__ __launch_bounds__(128) void proj_split(
    const float* __restrict__ actions, const float* __restrict__ fc_w,
    const float* __restrict__ fc_b)
{
    const int m = blockIdx.x, t = threadIdx.x;
    __shared__ float act[Adim];
    if (t < Adim) act[t] = actions[m * Adim + t];
    __syncthreads();
    const float a0 = act[0], a1 = act[1], a2 = act[2], a3 = act[3];
    const float a4 = act[4], a5 = act[5], a6 = act[6], a7 = act[7];
    __nv_bfloat16* dst = g_Axp + (size_t)m * KC;
#pragma unroll
    for (int j = 0; j < Hdim / 128; j++) {
        const int h = t + j * 128;
        const float4* wp = reinterpret_cast<const float4*>(fc_w + (size_t)h * Adim);
        const float4 w0 = wp[0], w1 = wp[1];
        float v = fc_b[h];
        v += a0 * w0.x + a1 * w0.y + a2 * w0.z + a3 * w0.w;
        v += a4 * w1.x + a5 * w1.y + a6 * w1.z + a7 * w1.w;
        v = fmaxf(v, 0.0f);
        const __nv_bfloat16 x1 = __float2bfloat16(v);
        const __nv_bfloat16 x2 = __float2bfloat16(v - __bfloat162float(x1));
        dst[h] = x1; dst[Hdim + h] = x1; dst[2 * Hdim + h] = x2;
    }
}

// ---------------- kernel 2: weight splits -------------------------------
__global__ __launch_bounds__(256) void split_w(
    const float* __restrict__ w_ih, const float* __restrict__ w_hh)
{
    const int bid = blockIdx.x;
    const float* src;
    __nv_bfloat16* dst;
    if (bid < G3H) {
        src = w_ih + (size_t)bid * Hdim;
        dst = g_Bih + (size_t)bid * KC;
    } else {
        const int j = bid - G3H, g = j % 3, i = j / 3;
        src = w_hh + (size_t)(g * Hdim + i) * Hdim;
        dst = g_Bhh + (size_t)j * KC;
    }
#pragma unroll
    for (int u = 0; u < Hdim / 256; u++) {
        const int k = threadIdx.x + u * 256;
        const float w = src[k];
        const __nv_bfloat16 w1 = __float2bfloat16(w);
        const __nv_bfloat16 w2 = __float2bfloat16(w - __bfloat162float(w1));
        dst[k] = w1; dst[Hdim + k] = w2; dst[2 * Hdim + k] = w1;
    }
}

// ---------------- kernel 3: split hidden + reset barrier ----------------
__global__ __launch_bounds__(256) void split_h0(const float* __restrict__ hidden)
{
    if (blockIdx.x == 0 && threadIdx.x == 0) { g_bar_count = 0; g_bar_flag = 0; }
    const int b = blockIdx.x;
    __nv_bfloat16* dst = g_Ah[0] + (size_t)b * KC;
    const float* src = hidden + (size_t)b * Hdim;
#pragma unroll
    for (int u = 0; u < Hdim / 256; u++) {
        const int k = threadIdx.x + u * 256;
        const float h = src[k];
        const __nv_bfloat16 h1 = __float2bfloat16(h);
        const __nv_bfloat16 h2 = __float2bfloat16(h - __bfloat162float(h1));
        dst[k] = h1; dst[Hdim + k] = h1; dst[2 * Hdim + k] = h2;
    }
}

// ---------------- kernel 4: xp GEMM via mma.sync (proven R4) ------------
#define XP_STAGE 28672
#define XP_SMEM  (4 * XP_STAGE)

__global__ __launch_bounds__(256) void xp_mma(const float* __restrict__ b_ih)
{
    extern __shared__ char sm[];
    const uint32_t smb = smem_to_u32(sm);
    const int tid = threadIdx.x, lane = tid & 31, wid = tid >> 5;
    const int nb = blockIdx.x, mb = blockIdx.y;

    uint32_t sdst[7]; const char* gsrc[7];
#pragma unroll
    for (int u = 0; u < 7; u++) {
        const int sidx = tid + u * 256;
        if (sidx < 1024) {
            const int row = sidx >> 3, s8 = sidx & 7;
            sdst[u] = SWZ((uint32_t)(row * 128 + s8 * 16));
            gsrc[u] = (const char*)g_Axp + (size_t)(mb * 128 + row) * (KC * 2) + s8 * 16;
        } else {
            const int bx = sidx - 1024, row = bx >> 3, s8 = bx & 7;
            sdst[u] = 16384u + SWZ((uint32_t)(row * 128 + s8 * 16));
            gsrc[u] = (const char*)g_Bih + (size_t)(nb * 96 + row) * (KC * 2) + s8 * 16;
        }
    }
    auto prefetch = [&](int c) {
        if (c < NCH) {
            const uint32_t sb = smb + (uint32_t)(c & 3) * XP_STAGE;
            const size_t off = (size_t)c * 128;
#pragma unroll
            for (int u = 0; u < 7; u++) CP_ASYNC16(sb + sdst[u], gsrc[u] + off);
        }
        CP_COMMIT();
    };

    const int mrow0 = (wid & 3) * 32, nc0 = (wid >> 2) * 48;
    const uint32_t ar0 = mrow0 + (lane & 15), ar1 = ar0 + 16;
    const uint32_t aoff0 = ar0 * 128, amk0 = (ar0 & 7) << 4;
    const uint32_t aoff1 = ar1 * 128, amk1 = (ar1 & 7) << 4;
    const uint32_t akh = (uint32_t)(lane >> 4) * 16;
    uint32_t boff[3], bmk[3];
#pragma unroll
    for (int p = 0; p < 3; p++) {
        const uint32_t nr = nc0 + p * 16 + (lane >> 4) * 8 + (lane & 7);
        boff[p] = 16384u + nr * 128; bmk[p] = (nr & 7) << 4;
    }
    const uint32_t bkh = (uint32_t)((lane >> 3) & 1) * 16;

    float acc[2][6][4] = {};
    prefetch(0); prefetch(1); prefetch(2);
    for (int c = 0; c < NCH; c++) {
        CP_WAIT2();
        __syncthreads();
        prefetch(c + 3);
        const uint32_t sb = smb + (uint32_t)(c & 3) * XP_STAGE;
#pragma unroll
        for (int s = 0; s < 4; s++) {
            uint32_t a0[4], a1[4], b[12];
            const uint32_t cA = akh + s * 32, cB = bkh + s * 32;
            ldsm4(a0, sb + aoff0 + (cA ^ amk0));
            ldsm4(a1, sb + aoff1 + (cA ^ amk1));
#pragma unroll
            for (int p = 0; p < 3; p++) ldsm4(b + 4 * p, sb + boff[p] + (cB ^ bmk[p]));
#pragma unroll
            for (int nt = 0; nt < 6; nt++) {
                mma16816(acc[0][nt], a0, b + 2 * nt);
                mma16816(acc[1][nt], a1, b + 2 * nt);
            }
        }
    }

    const int q = lane & 3, r4 = lane >> 2;
#pragma unroll
    for (int mg = 0; mg < 2; mg++) {
        const int row = mb * 128 + mrow0 + mg * 16 + r4;
#pragma unroll
        for (int nt = 0; nt < 6; nt++) {
            const int col = nb * 96 + nc0 + nt * 8 + 2 * q;
            const float2 bias = *reinterpret_cast<const float2*>(b_ih + col);
            float2 v0, v1;
            v0.x = acc[mg][nt][0] + bias.x; v0.y = acc[mg][nt][1] + bias.y;
            v1.x = acc[mg][nt][2] + bias.x; v1.y = acc[mg][nt][3] + bias.y;
            *reinterpret_cast<float2*>(g_xp + (size_t)row * G3H + col) = v0;
            *reinterpret_cast<float2*>(g_xp + (size_t)(row + 8) * G3H + col) = v1;
        }
    }
}

// ---------------- kernel 5: persistent GRU (all 256 steps) --------------
// 128 CTAs (nb 0..31, mb 0..3), 128 thr. Tile 32x96, K=3072, 4-stage pipe.
#define GR_STAGE 16384
#define GR_SMEM  (4 * GR_STAGE)
#define NBLK 128

__global__ __launch_bounds__(128) void gru_persist(
    const float* __restrict__ hidden,
    const float* __restrict__ b_hh, float* __restrict__ out)
{
    extern __shared__ char sm[];
    const uint32_t smb = smem_to_u32(sm);
    const int tid = threadIdx.x, lane = tid & 31, wid = tid >> 5;
    const int nb = blockIdx.x, mb = blockIdx.y;
    const int b0 = mb * 32, i0 = nb * 32;

    // ---- step-invariant address prep ----
    uint32_t sdst[8]; size_t aoff_g[2]; const char* bsrc[6];
#pragma unroll
    for (int u = 0; u < 8; u++) {
        const int sidx = tid + u * 128;
        if (sidx < 256) {
            const int row = sidx >> 3, s8 = sidx & 7;
            sdst[u] = SWZ((uint32_t)(row * 128 + s8 * 16));
            aoff_g[u] = (size_t)(b0 + row) * (KC * 2) + s8 * 16;
        } else {
            const int bx = sidx - 256, row = bx >> 3, s8 = bx & 7;
            sdst[u] = 4096u + SWZ((uint32_t)(row * 128 + s8 * 16));
            bsrc[u - 2] = (const char*)g_Bhh + (size_t)(nb * 96 + row) * (KC * 2) + s8 * 16;
        }
    }
    const int mrow0 = (wid & 1) * 16, nc0 = (wid >> 1) * 48;
    const uint32_t ar = mrow0 + (lane & 15);
    const uint32_t aoff = ar * 128, amk = (ar & 7) << 4;
    const uint32_t akh = (uint32_t)(lane >> 4) * 16;
    uint32_t boff[3], bmk[3];
#pragma unroll
    for (int p = 0; p < 3; p++) {
        const uint32_t nr = nc0 + p * 16 + (lane >> 4) * 8 + (lane & 7);
        boff[p] = 4096u + nr * 128; bmk[p] = (nr & 7) << 4;
    }
    const uint32_t bkh = (uint32_t)((lane >> 3) & 1) * 16;

    // ---- step-invariant epilogue state: h in regs, biases in regs ----
    float hv[8], bh0[8], bh1[8], bh2[8];
#pragma unroll
    for (int u = 0; u < 8; u++) {
        const int idx = tid + u * 128;
        const int b = b0 + (idx >> 5), i = i0 + (idx & 31);
        hv[u]  = hidden[(size_t)b * Hdim + i];
        bh0[u] = b_hh[i]; bh1[u] = b_hh[Hdim + i]; bh2[u] = b_hh[2 * Hdim + i];
    }

    for (int t = 0; t < Tdim; t++) {
        const char* Ab = (const char*)g_Ah[t & 1];
        float acc[6][4] = {};

        auto prefetch = [&](int c) {
            if (c < NCH) {
                const uint32_t sb = smb + (uint32_t)(c & 3) * GR_STAGE;
                const size_t off = (size_t)c * 128;
                CP_ASYNC16(sb + sdst[0], Ab + aoff_g[0] + off);
                CP_ASYNC16(sb + sdst[1], Ab + aoff_g[1] + off);
#pragma unroll
                for (int u = 0; u < 6; u++)
                    CP_ASYNC16(sb + sdst[u + 2], bsrc[u] + off);
            }
            CP_COMMIT();
        };

        prefetch(0); prefetch(1); prefetch(2);
        for (int c = 0; c < NCH; c++) {
            CP_WAIT2();
            __syncthreads();
            prefetch(c + 3);
            const uint32_t sb = smb + (uint32_t)(c & 3) * GR_STAGE;
#pragma unroll
            for (int s = 0; s < 4; s++) {
                uint32_t a[4], b[12];
                const uint32_t cA = akh + s * 32, cB = bkh + s * 32;
                ldsm4(a, sb + aoff + (cA ^ amk));
#pragma unroll
                for (int p = 0; p < 3; p++) ldsm4(b + 4 * p, sb + boff[p] + (cB ^ bmk[p]));
#pragma unroll
                for (int nt = 0; nt < 6; nt++) mma16816(acc[nt], a, b + 2 * nt);
            }
        }

        // stage hp [32][100] in smem (stage-0 region; all cp.async drained)
        float* hp = reinterpret_cast<float*>(sm);
        __syncthreads();
        {
            const int q = lane & 3, r0 = mrow0 + (lane >> 2);
#pragma unroll
            for (int nt = 0; nt < 6; nt++) {
                const int cc = nc0 + nt * 8 + 2 * q;
                hp[r0 * 100 + cc]           = acc[nt][0];
                hp[r0 * 100 + cc + 1]       = acc[nt][1];
                hp[(r0 + 8) * 100 + cc]     = acc[nt][2];
                hp[(r0 + 8) * 100 + cc + 1] = acc[nt][3];
            }
        }
        __syncthreads();

        __nv_bfloat16* Abase = g_Ah[(t & 1) ^ 1];
#pragma unroll
        for (int u = 0; u < 8; u++) {
            const int idx = tid + u * 128;
            const int bl = idx >> 5, il = idx & 31;
            const int b = b0 + bl, i = i0 + il;
            const float hr = hp[bl * 100 + 3 * il + 0] + bh0[u];
            const float hz = hp[bl * 100 + 3 * il + 1] + bh1[u];
            const float hn = hp[bl * 100 + 3 * il + 2] + bh2[u];
            const float* xpr = g_xp + ((size_t)b * Tdim + t) * G3H;
            const float xr = xpr[i], xz = xpr[Hdim + i], xn = xpr[2 * Hdim + i];
            const float rg = 1.0f / (1.0f + expf(-(xr + hr)));
            const float zg = 1.0f / (1.0f + expf(-(xz + hz)));
            const float ng = tanhf(xn + rg * hn);
            const float hnew = (1.0f - zg) * ng + zg * hv[u];
            hv[u] = hnew;
            out[((size_t)b * Tdim + t) * Hdim + i] = hnew;
            const __nv_bfloat16 h1 = __float2bfloat16(hnew);
            const __nv_bfloat16 h2 = __float2bfloat16(hnew - __bfloat162float(h1));
            __nv_bfloat16* An = Abase + (size_t)b * KC;
            An[i] = h1; An[Hdim + i] = h1; An[2 * Hdim + i] = h2;
        }

        // ---- device-wide barrier ----
        __syncthreads();
        if (tid == 0) {
            __threadfence();
            const unsigned prev = atomicAdd(&g_bar_count, 1u);
            if (prev == NBLK - 1) {
                g_bar_count = 0;
                __threadfence();
                atomicExch(&g_bar_flag, (unsigned)(t + 1));
            } else {
                while (atomicAdd(&g_bar_flag, 0u) < (unsigned)(t + 1))
                    __nanosleep(64);
            }
            __threadfence();
        }
        __syncthreads();
    }
}

// ---------------------------------------------------------------------------
extern "C" void kernel_launch(void* const* d_in, const int* in_sizes, int n_in,
                              void* d_out, int out_size)
{
    const float* actions = (const float*)d_in[0];
    const float* hidden  = (const float*)d_in[1];
    const float* fc_w    = (const float*)d_in[2];
    const float* fc_b    = (const float*)d_in[3];
    const float* w_ih    = (const float*)d_in[4];
    const float* w_hh    = (const float*)d_in[5];
    const float* b_ih    = (const float*)d_in[6];
    const float* b_hh    = (const float*)d_in[7];
    float* out = (float*)d_out;

    static bool attr_set = false;
    if (!attr_set) {
        cudaFuncSetAttribute(xp_mma, cudaFuncAttributeMaxDynamicSharedMemorySize, XP_SMEM);
        cudaFuncSetAttribute(gru_persist, cudaFuncAttributeMaxDynamicSharedMemorySize, GR_SMEM);
        attr_set = true;
    }

    proj_split<<<BT, 128>>>(actions, fc_w, fc_b);
    split_w<<<2 * G3H, 256>>>(w_ih, w_hh);
    split_h0<<<Bdim, 256>>>(hidden);
    xp_mma<<<dim3(32, 256), 256, XP_SMEM>>>(b_ih);
    gru_persist<<<dim3(32, 4), 128, GR_SMEM>>>(hidden, b_hh, out);
}